// round 7
// baseline (speedup 1.0000x reference)
#include <cuda_runtime.h>
#include <stdint.h>

#define NSTAGE 2
#define CH_ELEMS 4096u   // one 16KB chunk: [2 kt][32 nt][32 lane][2] tf32 (k16 slab)
#define CH_BYTES 16384u

// dynamic smem layout (bytes)
#define OFF_T 128u                               // t_range 25 f32
#define OFF_BW 256u                              // float2 (b1, wt)[256] -> 2048B
#define OFF_B2 2304u                             // f32 b2[256] -> 1024B
#define OFF_ZH 3584u                             // 64x256 tf32 in A-frag order = 65536B
#define OFF_RING (OFF_ZH + 65536u)               // 69120
#define DYN_SMEM (OFF_RING + NSTAGE * CH_BYTES)  // 101888 (~99.5KB, 2 CTAs/SM)

// prep output: 32 chunks (W1 slabs 0-15, W2 slabs 16-31) of 16KB in B-frag order
__device__ __align__(128) float g_wblk[32 * CH_ELEMS];

// ---------- helpers ----------
__device__ __forceinline__ uint32_t smem_u32(const void* p) {
    uint32_t a;
    asm("{ .reg .u64 t; cvta.to.shared.u64 t, %1; cvt.u32.u64 %0, t; }" : "=r"(a) : "l"(p));
    return a;
}
__device__ __forceinline__ float tf32r(float x) {
    float y; asm("cvt.rna.tf32.f32 %0, %1;" : "=f"(y) : "f"(x));
    return y;
}
__device__ __forceinline__ float tanh_acc(float x) {
    // tanh(x) = 1 - 2/(1 + e^{2x}); ex2/rcp approx ~2^-22 rel err; correct saturation.
    float u = x * 2.885390081777927f;  // 2*log2(e)
    float e; asm("ex2.approx.f32 %0, %1;" : "=f"(e) : "f"(u));
    float r; asm("rcp.approx.f32 %0, %1;" : "=f"(r) : "f"(e + 1.0f));
    return fmaf(-2.0f, r, 1.0f);
}

#define MBINIT(addr, cnt) \
    asm volatile("mbarrier.init.shared.b64 [%0], %1;" :: "r"(addr), "r"(cnt) : "memory")
#define MB_TX(addr, bytes) \
    asm volatile("mbarrier.arrive.expect_tx.shared.b64 _, [%0], %1;" :: "r"(addr), "r"(bytes) : "memory")
#define MB_ARRIVE(addr) \
    asm volatile("mbarrier.arrive.shared.b64 _, [%0];" :: "r"(addr) : "memory")

#define WAITP(addr, par) do { \
    uint32_t _m = (addr), _p = (par), _d; \
    asm volatile("{\n\t.reg .pred p;\n\t" \
        "mbarrier.try_wait.parity.acquire.cta.shared::cta.b64 p, [%1], %2;\n\t" \
        "selp.b32 %0, 1, 0, p;\n\t}" : "=r"(_d) : "r"(_m), "r"(_p) : "memory"); \
    if (!_d) { \
        asm volatile("{\n\t.reg .pred P1;\n\t" \
            "WL_%=:\n\t" \
            "mbarrier.try_wait.parity.acquire.cta.shared::cta.b64 P1, [%0], %1, 0x989680;\n\t" \
            "@P1 bra.uni WD_%=;\n\tbra.uni WL_%=;\n\tWD_%=:\n\t}" \
            :: "r"(_m), "r"(_p) : "memory"); \
    } \
} while (0)

#define WAITPR(addr, par) do { \
    uint32_t _m = (addr), _p = (par), _d; \
    asm volatile("{\n\t.reg .pred p;\n\t" \
        "mbarrier.try_wait.parity.relaxed.cta.shared::cta.b64 p, [%1], %2, 0x989680;\n\t" \
        "selp.b32 %0, 1, 0, p;\n\t}" : "=r"(_d) : "r"(_m), "r"(_p) : "memory"); \
    if (!_d) { \
        asm volatile("{\n\t.reg .pred P1;\n\t" \
            "WL_%=:\n\t" \
            "mbarrier.try_wait.parity.relaxed.cta.shared::cta.b64 P1, [%0], %1, 0x989680;\n\t" \
            "@P1 bra.uni WD_%=;\n\tbra.uni WL_%=;\n\tWD_%=:\n\t}" \
            :: "r"(_m), "r"(_p) : "memory"); \
    } \
} while (0)

#define BAR1() asm volatile("bar.sync 1, 256;" ::: "memory")

__device__ __forceinline__ void bulk_g2s(uint32_t dst, const void* src, uint32_t bytes, uint32_t mbar) {
    asm volatile(
        "cp.async.bulk.shared::cluster.global.mbarrier::complete_tx::bytes [%0], [%1], %2, [%3];"
        :: "r"(dst), "l"(src), "r"(bytes), "r"(mbar) : "memory");
}

// mma.sync m16n8k8 tf32 (g=lane>>2, t=lane&3):
// a0=(g,t) a1=(g+8,t) a2=(g,t+4) a3=(g+8,t+4); b0=(t,g) b1=(t+4,g);
// c0=(g,2t) c1=(g,2t+1) c2=(g+8,2t) c3=(g+8,2t+1)
#define MMA8(d, a, b) \
    asm volatile("mma.sync.aligned.m16n8k8.row.col.f32.tf32.tf32.f32 " \
        "{%0,%1,%2,%3}, {%4,%5,%6,%7}, {%8,%9}, {%0,%1,%2,%3};" \
        : "+f"((d)[0]), "+f"((d)[1]), "+f"((d)[2]), "+f"((d)[3]) \
        : "r"((a).x), "r"((a).y), "r"((a).z), "r"((a).w), "r"((b).x), "r"((b).y))

// A-fragment-order store into ZH: logical (row 0..63, col 0..255)
__device__ __forceinline__ void zh_store(float* ZH, int row, int col, float v) {
    int tile = ((row >> 4) << 5) + (col >> 3);
    int dl = ((row & 7) << 2) + (col & 3);
    int rr = ((row >> 3) & 1) + (((col >> 2) & 1) << 1);
    ZH[tile * 128 + dl * 4 + rr] = v;
}

// ---------- prep: tf32-round + B-fragment-order k16-slab images ----------
// chunk b = mat*16 + slab: B[k][n] = W[k][n], k in [slab*16, +16), n in [0,256)
// layout: idx = ((kt*32 + nt)*32 + lane)*2 + r ; k = slab*16+kt*8+(lane&3)+4r ; n = nt*8+(lane>>2)
extern "C" __global__ void __launch_bounds__(256) ode_prep(
    const float* __restrict__ W1, const float* __restrict__ W2) {
    int b = blockIdx.x, mat = b >> 4, slab = b & 15;
    const float* W = mat ? W2 : W1;
    for (int e = threadIdx.x; e < (int)CH_ELEMS; e += 256) {
        int r = e & 1, lane = (e >> 1) & 31, nt = (e >> 6) & 31, kt = e >> 11;
        int k = slab * 16 + kt * 8 + (lane & 3) + 4 * r;
        int n = nt * 8 + (lane >> 2);
        g_wblk[b * CH_ELEMS + e] = tf32r(W[k * 256 + n]);
    }
}

// ---------- GEMM pass: D[32x64 per warp] += A(ZH) @ B(ring), k=256 over 16 k16 chunks ----------
__device__ __forceinline__ void gemm_pass(
    float (&d)[2][8][4], const char* smem, uint32_t sb,
    int mi, int ni, int lane, uint32_t& cs, uint32_t& cp) {
    const uint4* A = (const uint4*)(smem + OFF_ZH);
    for (int kc = 0; kc < 16; kc++) {
        WAITP(sb + 16u * cs, cp);
        const uint2* Bk = (const uint2*)(smem + OFF_RING + cs * CH_BYTES);
#pragma unroll
        for (int kk = 0; kk < 2; kk++) {
            const int ktg = kc * 2 + kk;
            uint4 a[2];
#pragma unroll
            for (int i = 0; i < 2; i++) a[i] = A[((mi * 2 + i) * 32 + ktg) * 32 + lane];
            uint2 b[8];
#pragma unroll
            for (int j = 0; j < 8; j++) b[j] = Bk[(kk * 32 + ni * 8 + j) * 32 + lane];
#pragma unroll
            for (int i = 0; i < 2; i++)
#pragma unroll
                for (int j = 0; j < 8; j++) MMA8(d[i][j], a[i], b[j]);
        }
        if (lane == 0) MB_ARRIVE(sb + 48u + 16u * cs);
        cs++; if (cs == NSTAGE) { cs = 0; cp ^= 1; }
    }
}

// ---------- main persistent kernel ----------
// 256 CTAs x 64 rows, 2 CTAs/SM; warps 0-7 compute (2x4 grid of 32x64 tiles), warp 8 = producer.
extern "C" __global__ void __launch_bounds__(288, 2) ode_main(
    const float* __restrict__ z0, const float* __restrict__ t_range,
    const float* __restrict__ b1, const float* __restrict__ wt,
    const float* __restrict__ b2, float* __restrict__ out) {
    extern __shared__ char smem[];
    const uint32_t sb = smem_u32(smem);
    const int tid = threadIdx.x, w = tid >> 5, lane = tid & 31;
    const int row0 = blockIdx.x * 64;

    float* ZH = (float*)(smem + OFF_ZH);
    float* sT = (float*)(smem + OFF_T);
    float2* sBW = (float2*)(smem + OFF_BW);
    float* sB2 = (float*)(smem + OFF_B2);

    if (tid == 0) {
        for (int s = 0; s < NSTAGE; s++) {
            MBINIT(sb + 16u * s, 1);        // full: producer MB_TX(1 arrive) + bulk bytes
            MBINIT(sb + 48u + 16u * s, 8);  // empty: one arrive per compute warp
        }
    }
    if (tid < 256) {
        sB2[tid] = b2[tid];
        sBW[tid] = make_float2(b1[tid], wt[tid]);
        if (tid < 25) sT[tid] = t_range[tid];
        // init: z master -> out, tf32 image -> ZH (thread owns a quarter row)
        const int row = tid >> 2, cb = (tid & 3) * 64;
        const float4* zp = (const float4*)(z0 + (size_t)(row0 + row) * 256 + cb);
        float4* op = (float4*)(out + (size_t)(row0 + row) * 256 + cb);
#pragma unroll 4
        for (int q = 0; q < 16; q++) {
            float4 v = zp[q];
            op[q] = v;
            int c = cb + q * 4;
            zh_store(ZH, row, c + 0, tf32r(v.x));
            zh_store(ZH, row, c + 1, tf32r(v.y));
            zh_store(ZH, row, c + 2, tf32r(v.z));
            zh_store(ZH, row, c + 3, tf32r(v.w));
        }
    }
    __syncthreads();

    if (w == 8) {
        // ---- producer: 25 steps x 32 chunks (W1 slabs 0-15 then W2 slabs 16-31) ----
        if (lane == 0) {
            uint32_t es = 0, ep = 1;
            for (int i = 0; i < 800; i++) {
                WAITPR(sb + 48u + 16u * es, ep);
                MB_TX(sb + 16u * es, CH_BYTES);
                bulk_g2s(sb + OFF_RING + es * CH_BYTES, g_wblk + (i & 31) * CH_ELEMS,
                         CH_BYTES, sb + 16u * es);
                es++; if (es == NSTAGE) { es = 0; ep ^= 1; }
            }
        }
        return;
    }

    // ---- compute warps ----
    const int mi = w >> 2, ni = w & 3;  // warp tile: rows [mi*32,+32), cols [ni*64,+64)
    const int gid = lane >> 2, tig = lane & 3;
    const float dt = sT[1] - sT[0];
    uint32_t cs = 0, cp = 0;
    float d[2][8][4];

    for (int s = 0; s < 25; s++) {
        const float t = sT[s];
        // ---- GEMM1: D = z @ W1 ----
#pragma unroll
        for (int i = 0; i < 2; i++)
#pragma unroll
            for (int j = 0; j < 8; j++)
#pragma unroll
                for (int r = 0; r < 4; r++) d[i][j][r] = 0.0f;
        gemm_pass(d, smem, sb, mi, ni, lane, cs, cp);
        BAR1();  // all warps done reading ZH (z)
        // ---- h = tanh(D + b1 + t*wt) -> ZH (tf32, A-frag order; col is GEMM2's k) ----
#pragma unroll
        for (int i = 0; i < 2; i++)
#pragma unroll
            for (int j = 0; j < 8; j++)
#pragma unroll
                for (int r = 0; r < 4; r++) {
                    int row = mi * 32 + i * 16 + gid + ((r & 2) ? 8 : 0);
                    int col = ni * 64 + j * 8 + 2 * tig + (r & 1);
                    float2 bw = sBW[col];
                    float x = d[i][j][r] + bw.x + t * bw.y;
                    zh_store(ZH, row, col, tf32r(tanh_acc(x)));
                }
        BAR1();  // h fully written
        // ---- GEMM2: D = h @ W2 ----
#pragma unroll
        for (int i = 0; i < 2; i++)
#pragma unroll
            for (int j = 0; j < 8; j++)
#pragma unroll
                for (int r = 0; r < 4; r++) d[i][j][r] = 0.0f;
        gemm_pass(d, smem, sb, mi, ni, lane, cs, cp);
        BAR1();  // all warps done reading ZH (h)
        // ---- z update: z += dt*(D + b2); fp32 master in out, tf32 image -> ZH ----
#pragma unroll
        for (int i = 0; i < 2; i++)
#pragma unroll
            for (int j = 0; j < 8; j++)
#pragma unroll
                for (int rp = 0; rp < 2; rp++) {
                    int row = mi * 32 + i * 16 + gid + rp * 8;
                    int col = ni * 64 + j * 8 + 2 * tig;
                    size_t g = (size_t)(row0 + row) * 256 + col;
                    float2 zo = *(const float2*)(out + g);
                    float zn0 = fmaf(dt, d[i][j][2 * rp + 0] + sB2[col + 0], zo.x);
                    float zn1 = fmaf(dt, d[i][j][2 * rp + 1] + sB2[col + 1], zo.y);
                    *(float2*)(out + g) = make_float2(zn0, zn1);
                    zh_store(ZH, row, col + 0, tf32r(zn0));
                    zh_store(ZH, row, col + 1, tf32r(zn1));
                }
        BAR1();  // z image ready for next step's GEMM1
    }
}

extern "C" void kernel_launch(void* const* d_in, const int* in_sizes, int n_in,
                              void* d_out, int out_size) {
    const float* z0 = (const float*)d_in[0];
    const float* t_range = (const float*)d_in[1];
    const float* W1 = (const float*)d_in[2];
    const float* b1 = (const float*)d_in[3];
    const float* wt = (const float*)d_in[4];
    const float* W2 = (const float*)d_in[5];
    const float* b2 = (const float*)d_in[6];
    float* out = (float*)d_out;

    cudaFuncSetAttribute(ode_main, cudaFuncAttributeMaxDynamicSharedMemorySize, DYN_SMEM);
    ode_prep<<<32, 256>>>(W1, W2);
    ode_main<<<256, 288, DYN_SMEM>>>(z0, t_range, b1, wt, b2, out);
}

// round 9
// speedup vs baseline: 1.0097x; 1.0097x over previous
#include <cuda_runtime.h>
#include <stdint.h>

#define NSTAGE 5
#define CH_ELEMS 4096u   // one 16KB chunk: [2 kt][16 ntp][32 lane][4 w] tf32 (k16 slab)
#define CH_BYTES 16384u

// dynamic smem layout (bytes)
// mbars: full[5] @ 0..80, empty[5] @ 80..160
#define OFF_T 160u                               // t_range 25 f32
#define OFF_BW 384u                              // float2 (b1, wt)[256] -> 2048B
#define OFF_B2 2432u                             // f32 b2[256] -> 1024B
#define OFF_ZH 3584u                             // 128x256 tf32 in A-frag order = 131072B
#define OFF_RING (OFF_ZH + 131072u)              // 134656
#define DYN_SMEM (OFF_RING + NSTAGE * CH_BYTES)  // 216576

// prep output: 32 chunks (W1 slabs 0-15, W2 slabs 16-31) of 16KB, B-frag uint4-pair order
__device__ __align__(128) float g_wblk[32 * CH_ELEMS];

// ---------- helpers ----------
__device__ __forceinline__ uint32_t smem_u32(const void* p) {
    uint32_t a;
    asm("{ .reg .u64 t; cvta.to.shared.u64 t, %1; cvt.u32.u64 %0, t; }" : "=r"(a) : "l"(p));
    return a;
}
__device__ __forceinline__ float tf32r(float x) {
    float y; asm("cvt.rna.tf32.f32 %0, %1;" : "=f"(y) : "f"(x));
    return y;
}
__device__ __forceinline__ float tanh_acc(float x) {
    // tanh(x) = 1 - 2/(1 + e^{2x}); ex2/rcp approx ~2^-22 rel err; correct saturation.
    float u = x * 2.885390081777927f;  // 2*log2(e)
    float e; asm("ex2.approx.f32 %0, %1;" : "=f"(e) : "f"(u));
    float r; asm("rcp.approx.f32 %0, %1;" : "=f"(r) : "f"(e + 1.0f));
    return fmaf(-2.0f, r, 1.0f);
}

#define MBINIT(addr, cnt) \
    asm volatile("mbarrier.init.shared.b64 [%0], %1;" :: "r"(addr), "r"(cnt) : "memory")
#define MB_TX(addr, bytes) \
    asm volatile("mbarrier.arrive.expect_tx.shared.b64 _, [%0], %1;" :: "r"(addr), "r"(bytes) : "memory")
#define MB_ARRIVE(addr) \
    asm volatile("mbarrier.arrive.shared.b64 _, [%0];" :: "r"(addr) : "memory")

#define WAITP(addr, par) do { \
    uint32_t _m = (addr), _p = (par), _d; \
    asm volatile("{\n\t.reg .pred p;\n\t" \
        "mbarrier.try_wait.parity.acquire.cta.shared::cta.b64 p, [%1], %2;\n\t" \
        "selp.b32 %0, 1, 0, p;\n\t}" : "=r"(_d) : "r"(_m), "r"(_p) : "memory"); \
    if (!_d) { \
        asm volatile("{\n\t.reg .pred P1;\n\t" \
            "WL_%=:\n\t" \
            "mbarrier.try_wait.parity.acquire.cta.shared::cta.b64 P1, [%0], %1, 0x989680;\n\t" \
            "@P1 bra.uni WD_%=;\n\tbra.uni WL_%=;\n\tWD_%=:\n\t}" \
            :: "r"(_m), "r"(_p) : "memory"); \
    } \
} while (0)

#define WAITPR(addr, par) do { \
    uint32_t _m = (addr), _p = (par), _d; \
    asm volatile("{\n\t.reg .pred p;\n\t" \
        "mbarrier.try_wait.parity.relaxed.cta.shared::cta.b64 p, [%1], %2, 0x989680;\n\t" \
        "selp.b32 %0, 1, 0, p;\n\t}" : "=r"(_d) : "r"(_m), "r"(_p) : "memory"); \
    if (!_d) { \
        asm volatile("{\n\t.reg .pred P1;\n\t" \
            "WL_%=:\n\t" \
            "mbarrier.try_wait.parity.relaxed.cta.shared::cta.b64 P1, [%0], %1, 0x989680;\n\t" \
            "@P1 bra.uni WD_%=;\n\tbra.uni WL_%=;\n\tWD_%=:\n\t}" \
            :: "r"(_m), "r"(_p) : "memory"); \
    } \
} while (0)

#define BAR1() asm volatile("bar.sync 1, 512;" ::: "memory")

__device__ __forceinline__ void bulk_g2s(uint32_t dst, const void* src, uint32_t bytes, uint32_t mbar) {
    asm volatile(
        "cp.async.bulk.shared::cluster.global.mbarrier::complete_tx::bytes [%0], [%1], %2, [%3];"
        :: "r"(dst), "l"(src), "r"(bytes), "r"(mbar) : "memory");
}

// mma.sync m16n8k8 tf32 (g=lane>>2, t=lane&3):
// a0=(g,t) a1=(g+8,t) a2=(g,t+4) a3=(g+8,t+4); b0=(t,g) b1=(t+4,g);
// c0=(g,2t) c1=(g,2t+1) c2=(g+8,2t) c3=(g+8,2t+1)
#define MMA8(d, a, bx, by) \
    asm volatile("mma.sync.aligned.m16n8k8.row.col.f32.tf32.tf32.f32 " \
        "{%0,%1,%2,%3}, {%4,%5,%6,%7}, {%8,%9}, {%0,%1,%2,%3};" \
        : "+f"((d)[0]), "+f"((d)[1]), "+f"((d)[2]), "+f"((d)[3]) \
        : "r"((a).x), "r"((a).y), "r"((a).z), "r"((a).w), "r"(bx), "r"(by))

// A-fragment-order store into ZH: logical (row 0..127, col 0..255)
__device__ __forceinline__ void zh_store(float* ZH, int row, int col, float v) {
    int tile = ((row >> 4) << 5) + (col >> 3);
    int dl = ((row & 7) << 2) + (col & 3);
    int rr = ((row >> 3) & 1) + (((col >> 2) & 1) << 1);
    ZH[tile * 128 + dl * 4 + rr] = v;
}

// ---------- prep: tf32-round + B-frag uint4-pair k16-slab images ----------
// chunk b = mat*16 + slab: B[k][n] = W[k][n], k in [slab*16,+16), n in [0,256)
// idx e = ((kt*16 + ntp)*32 + lane)*4 + w   (w: bits 0-1, lane: 2-6, ntp: 7-10, kt: 11)
//   k = slab*16 + kt*8 + (lane&3) + 4*(w&1) ; n = (ntp*2 + (w>>1))*8 + (lane>>2)
// so one uint4 per lane = {b_j0.x, b_j0.y, b_j1.x, b_j1.y} for j0=2ntp', j1=2ntp'+1
extern "C" __global__ void __launch_bounds__(256) ode_prep(
    const float* __restrict__ W1, const float* __restrict__ W2) {
    int b = blockIdx.x, mat = b >> 4, slab = b & 15;
    const float* W = mat ? W2 : W1;
    for (int e = threadIdx.x; e < (int)CH_ELEMS; e += 256) {
        int w = e & 3, lane = (e >> 2) & 31, ntp = (e >> 7) & 15, kt = e >> 11;
        int k = slab * 16 + kt * 8 + (lane & 3) + 4 * (w & 1);
        int n = (ntp * 2 + (w >> 1)) * 8 + (lane >> 2);
        g_wblk[b * CH_ELEMS + e] = tf32r(W[k * 256 + n]);
    }
}

// ---------- GEMM pass: D[32x64 per warp] += A(ZH) @ B(ring), k=256 over 16 k16 chunks ----------
__device__ __forceinline__ void gemm_pass(
    float (&d)[2][8][4], const char* smem, uint32_t sb,
    int mi, int ni, int lane, uint32_t& cs, uint32_t& cp) {
    const uint4* A = (const uint4*)(smem + OFF_ZH);
    for (int kc = 0; kc < 16; kc++) {
        WAITP(sb + 16u * cs, cp);
        const uint4* Bk = (const uint4*)(smem + OFF_RING + cs * CH_BYTES);
#pragma unroll
        for (int kt = 0; kt < 2; kt++) {
            const int ktg = kc * 2 + kt;
            uint4 a[2];
#pragma unroll
            for (int i = 0; i < 2; i++) a[i] = A[((mi * 2 + i) * 32 + ktg) * 32 + lane];
            uint4 b4[4];
#pragma unroll
            for (int jp = 0; jp < 4; jp++) b4[jp] = Bk[(kt * 16 + ni * 4 + jp) * 32 + lane];
#pragma unroll
            for (int i = 0; i < 2; i++)
#pragma unroll
                for (int jp = 0; jp < 4; jp++) {
                    MMA8(d[i][2 * jp + 0], a[i], b4[jp].x, b4[jp].y);
                    MMA8(d[i][2 * jp + 1], a[i], b4[jp].z, b4[jp].w);
                }
        }
        if (lane == 0) MB_ARRIVE(sb + 80u + 16u * cs);
        cs++; if (cs == NSTAGE) { cs = 0; cp ^= 1; }
    }
}

// ---------- main persistent kernel ----------
// 128 CTAs x 128 rows; warps 0-15 compute (4x4 grid of 32x64 tiles), warp 16 = producer.
extern "C" __global__ void __launch_bounds__(544, 1) ode_main(
    const float* __restrict__ z0, const float* __restrict__ t_range,
    const float* __restrict__ b1, const float* __restrict__ wt,
    const float* __restrict__ b2, float* __restrict__ out) {
    extern __shared__ char smem[];
    const uint32_t sb = smem_u32(smem);
    const int tid = threadIdx.x, w = tid >> 5, lane = tid & 31;
    const int row0 = blockIdx.x * 128;

    float* ZH = (float*)(smem + OFF_ZH);
    float* sT = (float*)(smem + OFF_T);
    float2* sBW = (float2*)(smem + OFF_BW);
    float* sB2 = (float*)(smem + OFF_B2);

    if (tid == 0) {
        for (int s = 0; s < NSTAGE; s++) {
            MBINIT(sb + 16u * s, 1);         // full: producer MB_TX(1 arrive) + bulk bytes
            MBINIT(sb + 80u + 16u * s, 16);  // empty: one arrive per compute warp
        }
    }
    if (tid < 256) {
        sB2[tid] = b2[tid];
        sBW[tid] = make_float2(b1[tid], wt[tid]);
        if (tid < 25) sT[tid] = t_range[tid];
        // init: z master -> out, tf32 image -> ZH (thread owns half a row)
        const int row = tid >> 1, cb = (tid & 1) * 128;
        const float4* zp = (const float4*)(z0 + (size_t)(row0 + row) * 256 + cb);
        float4* op = (float4*)(out + (size_t)(row0 + row) * 256 + cb);
#pragma unroll 4
        for (int q = 0; q < 32; q++) {
            float4 v = zp[q];
            op[q] = v;
            int c = cb + q * 4;
            zh_store(ZH, row, c + 0, tf32r(v.x));
            zh_store(ZH, row, c + 1, tf32r(v.y));
            zh_store(ZH, row, c + 2, tf32r(v.z));
            zh_store(ZH, row, c + 3, tf32r(v.w));
        }
    }
    __syncthreads();

    if (w == 16) {
        // ---- producer: 25 steps x 32 chunks (W1 slabs 0-15 then W2 slabs 16-31) ----
        if (lane == 0) {
            uint32_t es = 0, ep = 1;
            for (int i = 0; i < 800; i++) {
                WAITPR(sb + 80u + 16u * es, ep);
                MB_TX(sb + 16u * es, CH_BYTES);
                bulk_g2s(sb + OFF_RING + es * CH_BYTES, g_wblk + (i & 31) * CH_ELEMS,
                         CH_BYTES, sb + 16u * es);
                es++; if (es == NSTAGE) { es = 0; ep ^= 1; }
            }
        }
        return;
    }

    // ---- compute warps ----
    const int mi = w >> 2, ni = w & 3;  // warp tile: rows [mi*32,+32), cols [ni*64,+64)
    const int gid = lane >> 2, tig = lane & 3;
    const float dt = sT[1] - sT[0];
    uint32_t cs = 0, cp = 0;
    float d[2][8][4];

    for (int s = 0; s < 25; s++) {
        const float t = sT[s];
        // ---- GEMM1: D = z @ W1 ----
#pragma unroll
        for (int i = 0; i < 2; i++)
#pragma unroll
            for (int j = 0; j < 8; j++)
#pragma unroll
                for (int r = 0; r < 4; r++) d[i][j][r] = 0.0f;
        gemm_pass(d, smem, sb, mi, ni, lane, cs, cp);
        BAR1();  // all warps done reading ZH (z)
        // ---- h = tanh(D + b1 + t*wt) -> ZH (tf32, A-frag order; col is GEMM2's k) ----
#pragma unroll
        for (int i = 0; i < 2; i++)
#pragma unroll
            for (int j = 0; j < 8; j++)
#pragma unroll
                for (int r = 0; r < 4; r++) {
                    int row = mi * 32 + i * 16 + gid + ((r & 2) ? 8 : 0);
                    int col = ni * 64 + j * 8 + 2 * tig + (r & 1);
                    float2 bw = sBW[col];
                    float x = d[i][j][r] + bw.x + t * bw.y;
                    zh_store(ZH, row, col, tf32r(tanh_acc(x)));
                }
        BAR1();  // h fully written
        // ---- GEMM2: D = h @ W2 ----
#pragma unroll
        for (int i = 0; i < 2; i++)
#pragma unroll
            for (int j = 0; j < 8; j++)
#pragma unroll
                for (int r = 0; r < 4; r++) d[i][j][r] = 0.0f;
        gemm_pass(d, smem, sb, mi, ni, lane, cs, cp);
        BAR1();  // all warps done reading ZH (h)
        // ---- z update: z += dt*(D + b2); fp32 master in out, tf32 image -> ZH ----
#pragma unroll
        for (int i = 0; i < 2; i++)
#pragma unroll
            for (int j = 0; j < 8; j++)
#pragma unroll
                for (int rp = 0; rp < 2; rp++) {
                    int row = mi * 32 + i * 16 + gid + rp * 8;
                    int col = ni * 64 + j * 8 + 2 * tig;
                    size_t g = (size_t)(row0 + row) * 256 + col;
                    float2 zo = *(const float2*)(out + g);
                    float zn0 = fmaf(dt, d[i][j][2 * rp + 0] + sB2[col + 0], zo.x);
                    float zn1 = fmaf(dt, d[i][j][2 * rp + 1] + sB2[col + 1], zo.y);
                    *(float2*)(out + g) = make_float2(zn0, zn1);
                    zh_store(ZH, row, col + 0, tf32r(zn0));
                    zh_store(ZH, row, col + 1, tf32r(zn1));
                }
        BAR1();  // z image ready for next step's GEMM1
    }
}

extern "C" void kernel_launch(void* const* d_in, const int* in_sizes, int n_in,
                              void* d_out, int out_size) {
    const float* z0 = (const float*)d_in[0];
    const float* t_range = (const float*)d_in[1];
    const float* W1 = (const float*)d_in[2];
    const float* b1 = (const float*)d_in[3];
    const float* wt = (const float*)d_in[4];
    const float* W2 = (const float*)d_in[5];
    const float* b2 = (const float*)d_in[6];
    float* out = (float*)d_out;

    cudaFuncSetAttribute(ode_main, cudaFuncAttributeMaxDynamicSharedMemorySize, DYN_SMEM);
    ode_prep<<<32, 256>>>(W1, W2);
    ode_main<<<128, 544, DYN_SMEM>>>(z0, t_range, b1, wt, b2, out);
}